// round 13
// baseline (speedup 1.0000x reference)
#include <cuda_runtime.h>

#define NN 50000      // num_nodes
#define TT 518        // num_timepoints
#define KK 32         // window
#define SS 3          // stride
#define LL 163        // (TT-KK)/SS + 1
#define HH 128        // hidden
#define EE 1600000    // edges

// scratch (allocation-free rule: __device__ globals)
__device__ float g_deg[NN];
__device__ float g_t[NN];
__device__ float g_s[LL];

// ---------------------------------------------------------------------------
// K0: init scratch (graph is replayed -> must reset every call)
// ---------------------------------------------------------------------------
__global__ void k_init() {
    int i = blockIdx.x * blockDim.x + threadIdx.x;
    if (i < NN) { g_deg[i] = 1.0f; g_t[i] = 0.0f; }   // deg includes self-loop +1
    if (i < LL) g_s[i] = 0.0f;
}

// ---------------------------------------------------------------------------
// K1: deg[col] += attr   (4 edges/thread, 128-bit loads)
// ---------------------------------------------------------------------------
__global__ void k_deg(const int* __restrict__ col, const float* __restrict__ attr) {
    int i = (blockIdx.x * blockDim.x + threadIdx.x) * 4;
    if (i < EE) {
        int4   c = *reinterpret_cast<const int4*>(col + i);
        float4 a = *reinterpret_cast<const float4*>(attr + i);
        atomicAdd(&g_deg[c.x], a.x);
        atomicAdd(&g_deg[c.y], a.y);
        atomicAdd(&g_deg[c.z], a.z);
        atomicAdd(&g_deg[c.w], a.w);
    }
}

// ---------------------------------------------------------------------------
// K2: t[row] += attr * rsqrt(deg[col])    (dinv computed on the fly)
// ---------------------------------------------------------------------------
__global__ void k_tacc(const int* __restrict__ row, const int* __restrict__ col,
                       const float* __restrict__ attr) {
    int i = (blockIdx.x * blockDim.x + threadIdx.x) * 4;
    if (i < EE) {
        int4   r = *reinterpret_cast<const int4*>(row + i);
        int4   c = *reinterpret_cast<const int4*>(col + i);
        float4 a = *reinterpret_cast<const float4*>(attr + i);
        atomicAdd(&g_t[r.x], a.x * rsqrtf(g_deg[c.x]));
        atomicAdd(&g_t[r.y], a.y * rsqrtf(g_deg[c.y]));
        atomicAdd(&g_t[r.z], a.z * rsqrtf(g_deg[c.z]));
        atomicAdd(&g_t[r.w], a.w * rsqrtf(g_deg[c.w]));
    }
}

// ---------------------------------------------------------------------------
// K3: fused depthwise conv + relu + weighted column-sum into s[163]
//
// One thread per node. L is processed in chunks of CL outputs kept in
// registers. The t'-major loop loads each x value ONCE and fans it out to all
// (j,k) pairs with 3j+k = t' (up to 11 FMAs per load) — all indices static
// after full unroll, so no dynamic register indexing.
// ---------------------------------------------------------------------------
template<int CL>
__device__ __forceinline__ void do_chunk(const float* __restrict__ xp,   // pre-offset to (3*l0, n)
                                         const float* __restrict__ w,    // 32 weights in regs
                                         int l0, float cn, float bias,
                                         float* __restrict__ s_part, int lane) {
    float acc[CL];
#pragma unroll
    for (int j = 0; j < CL; ++j) acc[j] = 0.0f;

    constexpr int NT = 3 * CL + KK - SS;   // timepoints covered by this chunk
#pragma unroll
    for (int tp = 0; tp < NT; ++tp) {
        float xv = xp[tp * NN];            // coalesced across threads (consecutive n)
#pragma unroll
        for (int j = 0; j < CL; ++j) {
            int k = tp - 3 * j;            // compile-time constant per (tp,j)
            if (k >= 0 && k < KK) acc[j] += w[k] * xv;
        }
    }

    // epilogue: relu+bias, scale by c[n], warp-tree reduce, one shared atomic per warp
#pragma unroll
    for (int j = 0; j < CL; ++j) {
        float v = cn * fmaxf(acc[j] + bias, 0.0f);
        v += __shfl_xor_sync(0xffffffffu, v, 16);
        v += __shfl_xor_sync(0xffffffffu, v, 8);
        v += __shfl_xor_sync(0xffffffffu, v, 4);
        v += __shfl_xor_sync(0xffffffffu, v, 2);
        v += __shfl_xor_sync(0xffffffffu, v, 1);
        if (lane == 0) atomicAdd(&s_part[l0 + j], v);
    }
}

__global__ void __launch_bounds__(256)
k_conv(const float* __restrict__ x,      // (T, N)
       const float* __restrict__ cw,     // (N, 32)
       const float* __restrict__ cb)     // (N,)
{
    __shared__ float s_part[LL];
    int tid = threadIdx.x;
    for (int i = tid; i < LL; i += 256) s_part[i] = 0.0f;
    __syncthreads();

    int n = blockIdx.x * 256 + tid;
    bool valid = (n < NN);
    int nn = valid ? n : (NN - 1);        // safe duplicate address for tail lanes

    float w[KK];
#pragma unroll
    for (int k = 0; k < KK; ++k) w[k] = cw[nn * KK + k];
    float bias = cb[nn];
    float dv = rsqrtf(g_deg[nn]);
    float cn = valid ? dv * (dv + g_t[nn]) : 0.0f;   // invalid lanes contribute 0

    int lane = tid & 31;
    const float* xp = x + nn;

    // 5 full chunks of 32 outputs (l = 0..159), then a 3-output tail (l = 160..162).
#pragma unroll 1
    for (int c = 0; c < 5; ++c)
        do_chunk<32>(xp + c * 96 * NN, w, c * 32, cn, bias, s_part, lane);
    do_chunk<3>(xp + 480 * NN, w, 160, cn, bias, s_part, lane);   // t up to 517 = T-1 exactly

    __syncthreads();
    for (int i = tid; i < LL; i += 256) atomicAdd(&g_s[i], s_part[i]);
}

// ---------------------------------------------------------------------------
// K4: out[h] = (1/N) * sum_k s[k]*W[k,h] + b[h]    (single block, tiny)
// ---------------------------------------------------------------------------
__global__ void k_final(const float* __restrict__ W,    // (L, H) row-major
                        const float* __restrict__ b,    // (H,)
                        float* __restrict__ out)        // (1, H)
{
    __shared__ float s_sh[LL];
    int h = threadIdx.x;
    for (int i = h; i < LL; i += HH) s_sh[i] = g_s[i];
    __syncthreads();
    float acc = 0.0f;
#pragma unroll 8
    for (int k = 0; k < LL; ++k) acc += s_sh[k] * W[k * HH + h];
    out[h] = acc * (1.0f / (float)NN) + b[h];
}

// ---------------------------------------------------------------------------
extern "C" void kernel_launch(void* const* d_in, const int* in_sizes, int n_in,
                              void* d_out, int out_size) {
    const float* x    = (const float*)d_in[0];   // (T, N)
    const int*   ei   = (const int*)  d_in[1];   // (2, E)
    const float* attr = (const float*)d_in[2];   // (E,)
    const float* cw   = (const float*)d_in[3];   // (N, 1, K)
    const float* cb   = (const float*)d_in[4];   // (N,)
    const float* W    = (const float*)d_in[5];   // (L, H)
    const float* b    = (const float*)d_in[6];   // (H,)
    float* out = (float*)d_out;                  // (1, H)

    const int* row = ei;
    const int* col = ei + EE;

    k_init <<<(NN + 255) / 256, 256>>>();
    k_deg  <<<(EE / 4 + 255) / 256, 256>>>(col, attr);
    k_tacc <<<(EE / 4 + 255) / 256, 256>>>(row, col, attr);
    k_conv <<<(NN + 255) / 256, 256>>>(x, cw, cb);
    k_final<<<1, HH>>>(W, b, out);
}

// round 14
// speedup vs baseline: 1.0049x; 1.0049x over previous
#include <cuda_runtime.h>

#define NN 50000      // num_nodes
#define TT 518        // num_timepoints
#define KK 32         // window
#define SS 3          // stride
#define LL 163        // (TT-KK)/SS + 1
#define HH 128        // hidden
#define EE 1600000    // edges

// scratch (allocation-free rule: __device__ globals)
__device__ float g_deg[NN];
__device__ float g_t[NN];
__device__ float g_s[LL];

// ---------------------------------------------------------------------------
// K0: init scratch (graph is replayed -> must reset every call)
// ---------------------------------------------------------------------------
__global__ void k_init() {
    int i = blockIdx.x * blockDim.x + threadIdx.x;
    if (i < NN) { g_deg[i] = 1.0f; g_t[i] = 0.0f; }   // deg includes self-loop +1
    if (i < LL) g_s[i] = 0.0f;
}

// ---------------------------------------------------------------------------
// K1: deg[col] += attr   (4 edges/thread, 128-bit loads)
// ---------------------------------------------------------------------------
__global__ void k_deg(const int* __restrict__ col, const float* __restrict__ attr) {
    int i = (blockIdx.x * blockDim.x + threadIdx.x) * 4;
    if (i < EE) {
        int4   c = *reinterpret_cast<const int4*>(col + i);
        float4 a = *reinterpret_cast<const float4*>(attr + i);
        atomicAdd(&g_deg[c.x], a.x);
        atomicAdd(&g_deg[c.y], a.y);
        atomicAdd(&g_deg[c.z], a.z);
        atomicAdd(&g_deg[c.w], a.w);
    }
}

// ---------------------------------------------------------------------------
// K2: t[row] += attr * rsqrt(deg[col])    (dinv computed on the fly)
// ---------------------------------------------------------------------------
__global__ void k_tacc(const int* __restrict__ row, const int* __restrict__ col,
                       const float* __restrict__ attr) {
    int i = (blockIdx.x * blockDim.x + threadIdx.x) * 4;
    if (i < EE) {
        int4   r = *reinterpret_cast<const int4*>(row + i);
        int4   c = *reinterpret_cast<const int4*>(col + i);
        float4 a = *reinterpret_cast<const float4*>(attr + i);
        atomicAdd(&g_t[r.x], a.x * rsqrtf(g_deg[c.x]));
        atomicAdd(&g_t[r.y], a.y * rsqrtf(g_deg[c.y]));
        atomicAdd(&g_t[r.z], a.z * rsqrtf(g_deg[c.z]));
        atomicAdd(&g_t[r.w], a.w * rsqrtf(g_deg[c.w]));
    }
}

// ---------------------------------------------------------------------------
// K3: fused depthwise conv + relu + weighted column-sum into s[163]
//
// One thread per node. L is processed in chunks of CL outputs kept in
// registers. The t'-major loop loads each x value ONCE and fans it out to all
// (j,k) pairs with 3j+k = t' (up to 11 FMAs per load) — all indices static
// after full unroll, so no dynamic register indexing.
// ---------------------------------------------------------------------------
template<int CL>
__device__ __forceinline__ void do_chunk(const float* __restrict__ xp,   // pre-offset to (3*l0, n)
                                         const float* __restrict__ w,    // 32 weights in regs
                                         int l0, float cn, float bias,
                                         float* __restrict__ s_part, int lane) {
    float acc[CL];
#pragma unroll
    for (int j = 0; j < CL; ++j) acc[j] = 0.0f;

    constexpr int NT = 3 * CL + KK - SS;   // timepoints covered by this chunk
#pragma unroll
    for (int tp = 0; tp < NT; ++tp) {
        float xv = xp[tp * NN];            // coalesced across threads (consecutive n)
#pragma unroll
        for (int j = 0; j < CL; ++j) {
            int k = tp - 3 * j;            // compile-time constant per (tp,j)
            if (k >= 0 && k < KK) acc[j] += w[k] * xv;
        }
    }

    // epilogue: relu+bias, scale by c[n], warp-tree reduce, one shared atomic per warp
#pragma unroll
    for (int j = 0; j < CL; ++j) {
        float v = cn * fmaxf(acc[j] + bias, 0.0f);
        v += __shfl_xor_sync(0xffffffffu, v, 16);
        v += __shfl_xor_sync(0xffffffffu, v, 8);
        v += __shfl_xor_sync(0xffffffffu, v, 4);
        v += __shfl_xor_sync(0xffffffffu, v, 2);
        v += __shfl_xor_sync(0xffffffffu, v, 1);
        if (lane == 0) atomicAdd(&s_part[l0 + j], v);
    }
}

__global__ void __launch_bounds__(256)
k_conv(const float* __restrict__ x,      // (T, N)
       const float* __restrict__ cw,     // (N, 32)
       const float* __restrict__ cb)     // (N,)
{
    __shared__ float s_part[LL];
    int tid = threadIdx.x;
    for (int i = tid; i < LL; i += 256) s_part[i] = 0.0f;
    __syncthreads();

    int n = blockIdx.x * 256 + tid;
    bool valid = (n < NN);
    int nn = valid ? n : (NN - 1);        // safe duplicate address for tail lanes

    float w[KK];
#pragma unroll
    for (int k = 0; k < KK; ++k) w[k] = cw[nn * KK + k];
    float bias = cb[nn];
    float dv = rsqrtf(g_deg[nn]);
    float cn = valid ? dv * (dv + g_t[nn]) : 0.0f;   // invalid lanes contribute 0

    int lane = tid & 31;
    const float* xp = x + nn;

    // 5 full chunks of 32 outputs (l = 0..159), then a 3-output tail (l = 160..162).
#pragma unroll 1
    for (int c = 0; c < 5; ++c)
        do_chunk<32>(xp + c * 96 * NN, w, c * 32, cn, bias, s_part, lane);
    do_chunk<3>(xp + 480 * NN, w, 160, cn, bias, s_part, lane);   // t up to 517 = T-1 exactly

    __syncthreads();
    for (int i = tid; i < LL; i += 256) atomicAdd(&g_s[i], s_part[i]);
}

// ---------------------------------------------------------------------------
// K4: out[h] = (1/N) * sum_k s[k]*W[k,h] + b[h]    (single block, tiny)
// ---------------------------------------------------------------------------
__global__ void k_final(const float* __restrict__ W,    // (L, H) row-major
                        const float* __restrict__ b,    // (H,)
                        float* __restrict__ out)        // (1, H)
{
    __shared__ float s_sh[LL];
    int h = threadIdx.x;
    for (int i = h; i < LL; i += HH) s_sh[i] = g_s[i];
    __syncthreads();
    float acc = 0.0f;
#pragma unroll 8
    for (int k = 0; k < LL; ++k) acc += s_sh[k] * W[k * HH + h];
    out[h] = acc * (1.0f / (float)NN) + b[h];
}

// ---------------------------------------------------------------------------
extern "C" void kernel_launch(void* const* d_in, const int* in_sizes, int n_in,
                              void* d_out, int out_size) {
    const float* x    = (const float*)d_in[0];   // (T, N)
    const int*   ei   = (const int*)  d_in[1];   // (2, E)
    const float* attr = (const float*)d_in[2];   // (E,)
    const float* cw   = (const float*)d_in[3];   // (N, 1, K)
    const float* cb   = (const float*)d_in[4];   // (N,)
    const float* W    = (const float*)d_in[5];   // (L, H)
    const float* b    = (const float*)d_in[6];   // (H,)
    float* out = (float*)d_out;                  // (1, H)

    const int* row = ei;
    const int* col = ei + EE;

    k_init <<<(NN + 255) / 256, 256>>>();
    k_deg  <<<(EE / 4 + 255) / 256, 256>>>(col, attr);
    k_tacc <<<(EE / 4 + 255) / 256, 256>>>(row, col, attr);
    k_conv <<<(NN + 255) / 256, 256>>>(x, cw, cb);
    k_final<<<1, HH>>>(W, b, out);
}

// round 15
// speedup vs baseline: 1.1695x; 1.1638x over previous
#include <cuda_runtime.h>

#define NN 50000      // num_nodes
#define TT 518        // num_timepoints
#define KK 32         // window
#define SS 3          // stride
#define LL 163        // (TT-KK)/SS + 1
#define HH 128        // hidden
#define EE 1600000    // edges

// scratch (allocation-free rule: __device__ globals)
__device__ float g_deg[NN];
__device__ float g_t[NN];
__device__ float g_s[LL];

// ---------------------------------------------------------------------------
// K0: init scratch (graph is replayed -> must reset every call)
// ---------------------------------------------------------------------------
__global__ void k_init() {
    int i = blockIdx.x * blockDim.x + threadIdx.x;
    if (i < NN) { g_deg[i] = 1.0f; g_t[i] = 0.0f; }   // deg includes self-loop +1
    if (i < LL) g_s[i] = 0.0f;
}

// ---------------------------------------------------------------------------
// K1: deg[col] += attr   (4 edges/thread, 128-bit loads)
// ---------------------------------------------------------------------------
__global__ void k_deg(const int* __restrict__ col, const float* __restrict__ attr) {
    int i = (blockIdx.x * blockDim.x + threadIdx.x) * 4;
    if (i < EE) {
        int4   c = *reinterpret_cast<const int4*>(col + i);
        float4 a = *reinterpret_cast<const float4*>(attr + i);
        atomicAdd(&g_deg[c.x], a.x);
        atomicAdd(&g_deg[c.y], a.y);
        atomicAdd(&g_deg[c.z], a.z);
        atomicAdd(&g_deg[c.w], a.w);
    }
}

// ---------------------------------------------------------------------------
// K2: t[row] += attr * rsqrt(deg[col])
// ---------------------------------------------------------------------------
__global__ void k_tacc(const int* __restrict__ row, const int* __restrict__ col,
                       const float* __restrict__ attr) {
    int i = (blockIdx.x * blockDim.x + threadIdx.x) * 4;
    if (i < EE) {
        int4   r = *reinterpret_cast<const int4*>(row + i);
        int4   c = *reinterpret_cast<const int4*>(col + i);
        float4 a = *reinterpret_cast<const float4*>(attr + i);
        atomicAdd(&g_t[r.x], a.x * rsqrtf(g_deg[c.x]));
        atomicAdd(&g_t[r.y], a.y * rsqrtf(g_deg[c.y]));
        atomicAdd(&g_t[r.z], a.z * rsqrtf(g_deg[c.z]));
        atomicAdd(&g_t[r.w], a.w * rsqrtf(g_deg[c.w]));
    }
}

// ---------------------------------------------------------------------------
// K3: fused depthwise conv + relu + weighted column-sum into s[163]
//
// blockIdx.x -> 128-node slab, blockIdx.y -> L-chunk (5 x 32 outputs + 3 tail).
// t'-major inner loop: each x load feeds up to 11 FMAs; all register indices
// are compile-time constants after full unroll.
// ---------------------------------------------------------------------------
template<int CL>
__device__ __forceinline__ void do_chunk(const float* __restrict__ xp,   // pre-offset to (t0, n)
                                         const float* __restrict__ w,    // 32 weights in regs
                                         float cn, float bias,
                                         float* __restrict__ s_part, int lane) {
    float acc[CL];
#pragma unroll
    for (int j = 0; j < CL; ++j) acc[j] = 0.0f;

    constexpr int NT = 3 * CL + KK - SS;   // timepoints covered by this chunk
#pragma unroll
    for (int tp = 0; tp < NT; ++tp) {
        float xv = xp[tp * NN];            // coalesced across threads (consecutive n)
#pragma unroll
        for (int j = 0; j < CL; ++j) {
            int k = tp - 3 * j;            // compile-time constant per (tp,j)
            if (k >= 0 && k < KK) acc[j] += w[k] * xv;
        }
    }

    // relu+bias, scale by c[n], warp-tree reduce, one shared atomic per warp
#pragma unroll
    for (int j = 0; j < CL; ++j) {
        float v = cn * fmaxf(acc[j] + bias, 0.0f);
        v += __shfl_xor_sync(0xffffffffu, v, 16);
        v += __shfl_xor_sync(0xffffffffu, v, 8);
        v += __shfl_xor_sync(0xffffffffu, v, 4);
        v += __shfl_xor_sync(0xffffffffu, v, 2);
        v += __shfl_xor_sync(0xffffffffu, v, 1);
        if (lane == 0) atomicAdd(&s_part[j], v);
    }
}

__global__ void __launch_bounds__(128, 6)
k_conv(const float* __restrict__ x,      // (T, N)
       const float* __restrict__ cw,     // (N, 32)
       const float* __restrict__ cb)     // (N,)
{
    __shared__ float s_part[32];
    int tid = threadIdx.x;
    if (tid < 32) s_part[tid] = 0.0f;
    __syncthreads();

    int n = blockIdx.x * 128 + tid;
    bool valid = (n < NN);
    int nn = valid ? n : (NN - 1);        // safe duplicate address for tail lanes

    float w[KK];
#pragma unroll
    for (int k = 0; k < KK; ++k) w[k] = cw[nn * KK + k];
    float bias = cb[nn];
    float dv = rsqrtf(g_deg[nn]);
    float cn = valid ? dv * (dv + g_t[nn]) : 0.0f;   // invalid lanes contribute 0

    int lane = tid & 31;
    int y = blockIdx.y;                   // chunk id: 0..4 full (32 outs), 5 = 3-out tail
    const float* xp = x + nn;

    if (y < 5) do_chunk<32>(xp + y * 96 * NN, w, cn, bias, s_part, lane);
    else       do_chunk<3>(xp + 480 * NN,     w, cn, bias, s_part, lane);  // t up to 517

    __syncthreads();
    int nout = (y < 5) ? 32 : 3;
    if (tid < nout) atomicAdd(&g_s[y * 32 + tid], s_part[tid]);
}

// ---------------------------------------------------------------------------
// K4: out[h] = (1/N) * sum_k s[k]*W[k,h] + b[h]    (single block, tiny)
// ---------------------------------------------------------------------------
__global__ void k_final(const float* __restrict__ W,    // (L, H) row-major
                        const float* __restrict__ b,    // (H,)
                        float* __restrict__ out)        // (1, H)
{
    __shared__ float s_sh[LL];
    int h = threadIdx.x;
    for (int i = h; i < LL; i += HH) s_sh[i] = g_s[i];
    __syncthreads();
    float acc = 0.0f;
#pragma unroll 8
    for (int k = 0; k < LL; ++k) acc += s_sh[k] * W[k * HH + h];
    out[h] = acc * (1.0f / (float)NN) + b[h];
}

// ---------------------------------------------------------------------------
extern "C" void kernel_launch(void* const* d_in, const int* in_sizes, int n_in,
                              void* d_out, int out_size) {
    const float* x    = (const float*)d_in[0];   // (T, N)
    const int*   ei   = (const int*)  d_in[1];   // (2, E)
    const float* attr = (const float*)d_in[2];   // (E,)
    const float* cw   = (const float*)d_in[3];   // (N, 1, K)
    const float* cb   = (const float*)d_in[4];   // (N,)
    const float* W    = (const float*)d_in[5];   // (L, H)
    const float* b    = (const float*)d_in[6];   // (H,)
    float* out = (float*)d_out;                  // (1, H)

    const int* row = ei;
    const int* col = ei + EE;

    k_init <<<(NN + 255) / 256, 256>>>();
    k_deg  <<<(EE / 4 + 255) / 256, 256>>>(col, attr);
    k_tacc <<<(EE / 4 + 255) / 256, 256>>>(row, col, attr);

    dim3 cgrid((NN + 127) / 128, 6);
    k_conv <<<cgrid, 128>>>(x, cw, cb);

    k_final<<<1, HH>>>(W, b, out);
}